// round 10
// baseline (speedup 1.0000x reference)
#include <cuda_runtime.h>

#define NB   128   // batch
#define ND   32    // dims
#define NP   16384 // N0*N1 pairs
#define NCTA 296   // 2 CTAs per SM (guaranteed by __launch_bounds__(512,2))
#define THREADS 512
#define TILE 56    // pairs per CTA, zero-padded (max actual = 56)
#define GROUPS 2
#define PPT (TILE/GROUPS)   // 28 pairs per group
#define PSTRIDE 33 // 32 num + 1 den

typedef unsigned long long u64;

__device__ float g_partial[NCTA * NB * PSTRIDE];
__device__ unsigned int g_arrive;   // monotonic across graph replays

// ---- packed f32x2 helpers (Blackwell FFMA2/FADD2: PTX-only) ----
__device__ __forceinline__ u64 fma2(u64 a, u64 b, u64 c) {
    u64 d;
    asm("fma.rn.f32x2 %0, %1, %2, %3;" : "=l"(d) : "l"(a), "l"(b), "l"(c));
    return d;
}
__device__ __forceinline__ u64 add2(u64 a, u64 b) {
    u64 d;
    asm("add.rn.f32x2 %0, %1, %2;" : "=l"(d) : "l"(a), "l"(b));
    return d;
}
__device__ __forceinline__ u64 pack2(float lo, float hi) {
    u64 d;
    asm("mov.b64 %0, {%1, %2};" : "=l"(d) : "f"(lo), "f"(hi));
    return d;
}
__device__ __forceinline__ void unpack2(u64 v, float& lo, float& hi) {
    asm("mov.b64 {%0, %1}, %2;" : "=f"(lo), "=f"(hi) : "l"(v));
}

// ---------------------------------------------------------------------------
// Occupancy-first variant of the R9 quartet kernel:
//   2 batches/thread  -> ~34 regs of state -> 64-reg cap -> 2 CTAs/SM (32 warps).
// Warp layout: wg = wid&1 (pair group 0..1), wb = wid>>1 (batch block of 16).
// Lane: q = lane&3 (dim quarter), s = lane>>2 (slot 0..7).
// Thread batches: b_r = wb*16 + r*8 + s, r = 0..1. Dims: q*8 .. q*8+7.
// logw = quartet shfl-xor sum (commutative pairs -> bit-deterministic).
// Each CTA owns ~55 pairs (one zero-padded 56-pair tile) x all 128 batches.
// ---------------------------------------------------------------------------
__global__ __launch_bounds__(THREADS, 2)
void gmm_all(const float* __restrict__ X,   const float* __restrict__ t_ptr,
             const float* __restrict__ Mu0, const float* __restrict__ Mu1,
             const float* __restrict__ S0,  const float* __restrict__ S1,
             const float* __restrict__ Lam, float* __restrict__ out)
{
    __shared__ __align__(16) float s_p2[TILE * ND];
    __shared__ __align__(16) float s_p1[TILE * ND];
    __shared__ __align__(16) float s_pk[TILE * ND];
    __shared__ __align__(16) float s_pc[TILE * ND];
    __shared__ float s_p0[TILE];
    __shared__ float s_lam[TILE];
    __shared__ float s_red[NB * PSTRIDE];   // 16.9 KB; total static ~46 KB

    const int tid  = threadIdx.x;
    const int wid  = tid >> 5;
    const int lane = tid & 31;

    const int q  = lane & 3;          // dim quarter (0..3)
    const int s  = lane >> 2;         // batch slot (0..7)
    const int wg = wid & 1;           // pair group (0..1)
    const int wb = wid >> 1;          // batch block (0..7), 16 batches each

    // balanced contiguous pair range for this CTA (55 or 56 pairs)
    const int cta     = blockIdx.x;
    const int basecnt = NP / NCTA;            // 55
    const int rem     = NP - basecnt * NCTA;  // 104
    const int start   = cta * basecnt + (cta < rem ? cta : rem);
    const int np      = basecnt + (cta < rem ? 1 : 0);

    const float t     = t_ptr[0];
    const float omt   = 1.0f - t;
    const float e2    = 0.25f;     // eps^2 (eps = 0.5)
    const float e4    = 0.0625f;   // eps^4
    const float tt    = t * t;
    const float omt2  = omt * omt;
    const float t2omt = 2.0f * t * omt;
    const float e2tot = e2 * t * omt;

    // x for 2 batches x 8 dims: 8 packed f32x2 (16 regs)
    u64 xq[2][4];
    #pragma unroll
    for (int r = 0; r < 2; r++) {
        const int br = wb * 16 + r * 8 + s;
        const ulonglong2* xg = (const ulonglong2*)(X + br * ND + q * 8);
        const ulonglong2 v0 = xg[0];
        const ulonglong2 v1 = xg[1];
        xq[r][0] = v0.x; xq[r][1] = v0.y;
        xq[r][2] = v1.x; xq[r][3] = v1.y;
    }

    float den[2] = {0.f, 0.f};
    u64 numq[2][4];
    #pragma unroll
    for (int r = 0; r < 2; r++)
        #pragma unroll
        for (int c = 0; c < 4; c++) numq[r][c] = 0ull;

    // ---- coefficient phase: warp per pair, lane per dim (coalesced) ----
    for (int p = wid; p < np; p += THREADS / 32) {
        const int ij = start + p;
        const int i  = ij >> 7;
        const int j  = ij & 127;

        const float lam = Lam[ij];

        const float s0 = S0[i * ND + lane];
        const float s1 = S1[j * ND + lane];
        const float Ds = sqrtf(fmaf(4.0f * s0, s1, e4));
        const float Cs = 0.5f * (Ds - e2);
        const float Sigma = omt2 * s0 + tt * s1 + t2omt * Cs + e2tot;
        const float St = (t * s1 + omt * Cs) - (omt * s0 + t * Cs) - e2 * t;

        const float mu0 = Mu0[i * ND + lane];
        const float mu1 = Mu1[j * ND + lane];
        const float mut = fmaf(t, mu1, omt * mu0);

        const float inv = __fdividef(1.0f, Sigma);
        const float K   = St * inv;
        const float a   = -0.5f * inv;

        s_p2[p * ND + lane] = a;
        s_p1[p * ND + lane] = inv * mut;
        s_pk[p * ND + lane] = K;
        s_pc[p * ND + lane] = (mu1 - mu0) - K * mut;

        float p0 = fmaf(a * mut, mut, -0.5f * __logf(Sigma));
        #pragma unroll
        for (int off = 16; off; off >>= 1)
            p0 += __shfl_xor_sync(0xFFFFFFFFu, p0, off);
        if (lane == 0) { s_p0[p] = p0; s_lam[p] = lam; }
    }
    // zero-pad tail pairs: lam=0 -> w==0 exactly, no NaNs
    for (int p = np + wid; p < TILE; p += THREADS / 32) {
        s_p2[p * ND + lane] = 0.0f;
        s_p1[p * ND + lane] = 0.0f;
        s_pk[p * ND + lane] = 0.0f;
        s_pc[p * ND + lane] = 0.0f;
        if (lane == 0) { s_p0[p] = 0.0f; s_lam[p] = 0.0f; }
    }
    __syncthreads();

    // ---- accumulate: group wg takes pairs p = wg, wg+2, ... (28 each) ----
    #pragma unroll 2
    for (int pp = 0; pp < PPT; pp++) {
        const int p   = wg + pp * GROUPS;
        const int off = p * ND + q * 8;

        const ulonglong2 aA = *(const ulonglong2*)(s_p2 + off);
        const ulonglong2 aB = *(const ulonglong2*)(s_p2 + off + 4);
        const ulonglong2 bA = *(const ulonglong2*)(s_p1 + off);
        const ulonglong2 bB = *(const ulonglong2*)(s_p1 + off + 4);
        const float p0  = s_p0[p];
        const float lam = s_lam[p];

        float w_[2];
        #pragma unroll
        for (int r = 0; r < 2; r++) {
            const u64 t0 = fma2(aA.x, xq[r][0], bA.x);
            const u64 t1 = fma2(aA.y, xq[r][1], bA.y);
            const u64 t2 = fma2(aB.x, xq[r][2], bB.x);
            const u64 t3 = fma2(aB.y, xq[r][3], bB.y);
            u64 acc0 = fma2(t0, xq[r][0], 0ull);
            u64 acc1 = fma2(t1, xq[r][1], 0ull);
            acc0 = fma2(t2, xq[r][2], acc0);
            acc1 = fma2(t3, xq[r][3], acc1);
            float lo, hi;
            unpack2(add2(acc0, acc1), lo, hi);
            float part = lo + hi;                       // this quarter
            part += __shfl_xor_sync(0xFFFFFFFFu, part, 1);
            part += __shfl_xor_sync(0xFFFFFFFFu, part, 2);
            const float logw = fminf(fmaxf(part + p0, -50.0f), 50.0f);
            w_[r] = __expf(logw) * lam;
            den[r] += w_[r];
        }

        const ulonglong2 kA = *(const ulonglong2*)(s_pk + off);
        const ulonglong2 kB = *(const ulonglong2*)(s_pk + off + 4);
        const ulonglong2 cA = *(const ulonglong2*)(s_pc + off);
        const ulonglong2 cB = *(const ulonglong2*)(s_pc + off + 4);
        #pragma unroll
        for (int r = 0; r < 2; r++) {
            const u64 w2 = pack2(w_[r], w_[r]);
            numq[r][0] = fma2(fma2(kA.x, xq[r][0], cA.x), w2, numq[r][0]);
            numq[r][1] = fma2(fma2(kA.y, xq[r][1], cA.y), w2, numq[r][1]);
            numq[r][2] = fma2(fma2(kB.x, xq[r][2], cB.x), w2, numq[r][2]);
            numq[r][3] = fma2(fma2(kB.y, xq[r][3], cB.y), w2, numq[r][3]);
        }
    }
    __syncthreads();

    // ---- group combine: fixed order wg = 0,1 (deterministic) ----
    for (int gg = 0; gg < GROUPS; gg++) {
        if (wg == gg) {
            #pragma unroll
            for (int r = 0; r < 2; r++) {
                const int br = wb * 16 + r * 8 + s;
                float* my = s_red + br * PSTRIDE + q * 8;
                float f[8];
                unpack2(numq[r][0], f[0], f[1]);
                unpack2(numq[r][1], f[2], f[3]);
                unpack2(numq[r][2], f[4], f[5]);
                unpack2(numq[r][3], f[6], f[7]);
                if (gg == 0) {
                    #pragma unroll
                    for (int k = 0; k < 8; k++) my[k] = f[k];
                    if (q == 0) s_red[br * PSTRIDE + 32] = den[r];
                } else {
                    #pragma unroll
                    for (int k = 0; k < 8; k++) my[k] += f[k];
                    if (q == 0) s_red[br * PSTRIDE + 32] += den[r];
                }
            }
        }
        __syncthreads();
    }

    // write this CTA's partial to global
    {
        float* gp = g_partial + (size_t)cta * NB * PSTRIDE;
        for (int k = tid; k < NB * PSTRIDE; k += THREADS)
            gp[k] = s_red[k];
    }

    // ---- grid-wide arrival barrier (release-arrive, acquire-spin) ----
    // Safe: __launch_bounds__(512,2) + 46KB smem guarantee all 296 CTAs
    // co-resident (one wave).
    __threadfence();
    __syncthreads();
    if (tid == 0) {
        const unsigned ticket = atomicAdd(&g_arrive, 1u);
        if (cta < NB) {
            const unsigned target = (ticket / NCTA + 1u) * NCTA;
            unsigned v;
            do {
                asm volatile("ld.acquire.gpu.global.u32 %0, [%1];"
                             : "=r"(v) : "l"(&g_arrive));
            } while (v < target);
        }
    }
    if (cta >= NB) return;       // non-reducing CTAs exit after arriving
    __syncthreads();

    // ---- final reduce: this CTA owns batch = cta ----
    {
        const int w2i = tid >> 5;
        const int ln  = tid & 31;
        const float* bp = g_partial + cta * PSTRIDE;

        float acc[3] = {0.f, 0.f, 0.f};
        const int nn[3] = {w2i, w2i + 16, 32};
        #pragma unroll
        for (int r = 0; r < 3; r++) {
            #pragma unroll
            for (int i = 0; i < 10; i++) {
                const int c = ln + 32 * i;
                if (c < NCTA)
                    acc[r] += __ldcg(bp + (size_t)c * NB * PSTRIDE + nn[r]);
            }
        }
        #pragma unroll
        for (int r = 0; r < 3; r++) {
            #pragma unroll
            for (int off = 16; off; off >>= 1)
                acc[r] += __shfl_xor_sync(0xFFFFFFFFu, acc[r], off);
        }
        __syncthreads();   // s_red reuse: all prior readers done
        if (ln == 0) {
            s_red[nn[0]] = acc[0];
            s_red[nn[1]] = acc[1];
            if (w2i == 0) s_red[32] = acc[2];
        }
    }
    __syncthreads();

    if (tid < ND)
        out[cta * ND + tid] = s_red[tid] / s_red[32];
}

// ---------------------------------------------------------------------------
extern "C" void kernel_launch(void* const* d_in, const int* in_sizes, int n_in,
                              void* d_out, int out_size)
{
    const float* X   = (const float*)d_in[0];
    const float* t   = (const float*)d_in[1];
    const float* Mu0 = (const float*)d_in[2];
    const float* Mu1 = (const float*)d_in[3];
    const float* S0  = (const float*)d_in[4];
    const float* S1  = (const float*)d_in[5];
    const float* Lam = (const float*)d_in[6];
    float* out = (float*)d_out;

    gmm_all<<<NCTA, THREADS>>>(X, t, Mu0, Mu1, S0, S1, Lam, out);
}